// round 4
// baseline (speedup 1.0000x reference)
#include <cuda_runtime.h>

// DiscreteContinuousConvS2: fused DISCO gather + channel-contraction GEMM.
// Entry layout (guaranteed by setup_inputs): e = k*(181*24) + ho*24 + j,
// lat_in in {ho-1,ho,ho+1} clipped, longitude contraction is circular shift.

namespace {
constexpr int B_  = 2;
constexpr int C_  = 64;   // C_in
constexpr int F_  = 64;   // C_out
constexpr int H_  = 181;  // nlat
constexpr int W_  = 360;  // nlon
constexpr int K_  = 9;    // kernel functions
constexpr int J_  = 24;   // nnz per (k, lat_out)

constexpr int CCH = 8;            // channels per chunk
constexpr int NCH = C_ / CCH;     // 8 chunks
constexpr int WT  = 64;           // wo tile width
constexpr int SXP = W_ + WT;      // 424: wrap-padded x row pitch (floats)
constexpr int CKL = CCH * K_;     // 72 (c,k) pairs per chunk
constexpr int SYP = WT + 4;       // 68: y row pitch (bank-conflict pad)
constexpr int NT  = 256;          // threads per CTA

constexpr int SX_FLOATS = CCH * 3 * SXP;  // 10176
constexpr int SY_FLOATS = CKL * SYP;      // 4896
constexpr int SW_FLOATS = CKL * F_;       // 4608
constexpr size_t SMEM_BYTES =
    (size_t)(SX_FLOATS + SY_FLOATS + SW_FLOATS) * 4 + (size_t)K_ * J_ * 8;
}

// weight transposed to [c*K+k][f] so per-chunk smem fill is contiguous
__device__ float g_wT[C_ * K_ * F_];

__global__ void transpose_w_kernel(const float* __restrict__ w) {
  int i = blockIdx.x * blockDim.x + threadIdx.x;
  if (i < C_ * K_ * F_) {
    int f  = i & (F_ - 1);
    int ck = i >> 6;
    // w layout: [F][C][K] -> flat f*(C*K) + c*K + k = f*576 + ck
    g_wT[i] = w[f * (C_ * K_) + ck];
  }
}

__global__ __launch_bounds__(NT, 2)
void disco_kernel(const float* __restrict__ x,
                  const float* __restrict__ psi_vals,
                  const float* __restrict__ bias,
                  const int*   __restrict__ psi_lat_in,
                  const int*   __restrict__ psi_lon_in,
                  float*       __restrict__ out) {
  extern __shared__ float smem[];
  float*  sx = smem;                       // [CCH][3][SXP]
  float*  sy = sx + SX_FLOATS;             // [CKL][SYP]
  float*  sw = sy + SY_FLOATS;             // [CKL][F_]
  float2* se = (float2*)(sw + SW_FLOATS);  // [K_*J_] {psi, offset-as-int}

  const int t  = threadIdx.x;
  const int ho = blockIdx.y;
  const int b  = blockIdx.z;
  // 6 tiles: 0,64,128,192,256, and last shifted to 296 (overlap recompute)
  const int wb = (blockIdx.x == 5) ? (W_ - WT) : blockIdx.x * WT;

  // ---- build per-ho entry table, rebased by wb ----
  if (t < K_ * J_) {
    int k = t / J_;
    int j = t - k * J_;
    int e = (k * H_ + ho) * J_ + j;
    int li  = psi_lat_in[e] - (ho - 1);       // local lat row 0..2
    int lon = psi_lon_in[e] + wb;
    if (lon >= W_) lon -= W_;                 // rebased start lon (0..359)
    int off = li * SXP + lon;                 // smem offset within channel slab
    se[t] = make_float2(psi_vals[e], __int_as_float(off));
  }

  // ---- accumulators: thread owns (f = t&63, 16 consecutive wo) ----
  const int f  = t & (F_ - 1);
  const int wg = t >> 6;            // 0..3 -> wo sub-block wg*16
  float acc[16];
  {
    float bv = bias[f];
#pragma unroll
    for (int i = 0; i < 16; i++) acc[i] = bv;
  }

  for (int ch = 0; ch < NCH; ch++) {
    const int c0 = ch * CCH;
    __syncthreads();  // entry table ready / previous GEMM reads done

    // ---- stage x slice: channels [c0,c0+8), lat rows ho-1..ho+1 (clamped),
    //      width 424 (360 + 64 wrap tail) ----
    for (int i = t; i < SX_FLOATS; i += NT) {
      int c = i / (3 * SXP);
      int r = i - c * (3 * SXP);
      int l = r / SXP;
      int w = r - l * SXP;
      int hr = ho - 1 + l;
      hr = (hr < 0) ? 0 : (hr > H_ - 1 ? H_ - 1 : hr);
      int gw = (w < W_) ? w : (w - W_);
      sx[i] = x[((b * C_ + c0 + c) * H_ + hr) * W_ + gw];
    }
    // ---- stage transposed weight chunk (contiguous) ----
    {
      const float4* wsrc = (const float4*)(g_wT + c0 * K_ * F_);
      float4* wdst = (float4*)sw;
      for (int i = t; i < SW_FLOATS / 4; i += NT) wdst[i] = wsrc[i];
    }
    __syncthreads();

    // ---- gather: y[ck][wo] = sum_j psi * x[c, lat_in, lon+wo] ----
    for (int s = t; s < CKL * 4; s += NT) {
      int ck = s >> 2;
      int wq = (s & 3) << 4;                       // 0,16,32,48
      const float*  sxc = sx + (ck / K_) * (3 * SXP);
      const float2* sek = se + (ck % K_) * J_;
      float y[16];
#pragma unroll
      for (int i = 0; i < 16; i++) y[i] = 0.f;
#pragma unroll 4
      for (int j = 0; j < J_; j++) {
        float2 pe = sek[j];
        const float* p = sxc + __float_as_int(pe.y) + wq;
        float ps = pe.x;
#pragma unroll
        for (int i = 0; i < 16; i++) y[i] = fmaf(ps, p[i], y[i]);
      }
      float4* yo = (float4*)(sy + ck * SYP + wq);
      yo[0] = make_float4(y[0],  y[1],  y[2],  y[3]);
      yo[1] = make_float4(y[4],  y[5],  y[6],  y[7]);
      yo[2] = make_float4(y[8],  y[9],  y[10], y[11]);
      yo[3] = make_float4(y[12], y[13], y[14], y[15]);
    }
    __syncthreads();

    // ---- GEMM: acc[f][wo] += sum_ck w[ck][f] * y[ck][wo] ----
#pragma unroll 2
    for (int ck = 0; ck < CKL; ck++) {
      float wv = sw[ck * F_ + f];
      const float4* yp = (const float4*)(sy + ck * SYP) + (wg << 2);
      float4 a0 = yp[0], a1 = yp[1], a2 = yp[2], a3 = yp[3];
      acc[0]  = fmaf(wv, a0.x, acc[0]);
      acc[1]  = fmaf(wv, a0.y, acc[1]);
      acc[2]  = fmaf(wv, a0.z, acc[2]);
      acc[3]  = fmaf(wv, a0.w, acc[3]);
      acc[4]  = fmaf(wv, a1.x, acc[4]);
      acc[5]  = fmaf(wv, a1.y, acc[5]);
      acc[6]  = fmaf(wv, a1.z, acc[6]);
      acc[7]  = fmaf(wv, a1.w, acc[7]);
      acc[8]  = fmaf(wv, a2.x, acc[8]);
      acc[9]  = fmaf(wv, a2.y, acc[9]);
      acc[10] = fmaf(wv, a2.z, acc[10]);
      acc[11] = fmaf(wv, a2.w, acc[11]);
      acc[12] = fmaf(wv, a3.x, acc[12]);
      acc[13] = fmaf(wv, a3.y, acc[13]);
      acc[14] = fmaf(wv, a3.z, acc[14]);
      acc[15] = fmaf(wv, a3.w, acc[15]);
    }
  }

  // ---- write out[b][f][ho][wb + wg*16 .. +15] ----
  float4* o4 = (float4*)(out + (((b * F_ + f) * H_ + ho) * W_ + wb + (wg << 4)));
  o4[0] = make_float4(acc[0],  acc[1],  acc[2],  acc[3]);
  o4[1] = make_float4(acc[4],  acc[5],  acc[6],  acc[7]);
  o4[2] = make_float4(acc[8],  acc[9],  acc[10], acc[11]);
  o4[3] = make_float4(acc[12], acc[13], acc[14], acc[15]);
}

extern "C" void kernel_launch(void* const* d_in, const int* in_sizes, int n_in,
                              void* d_out, int out_size) {
  const float* x          = (const float*)d_in[0];
  const float* psi_vals   = (const float*)d_in[1];
  const float* weight     = (const float*)d_in[2];
  const float* bias       = (const float*)d_in[3];
  const int*   psi_lat_in = (const int*)  d_in[6];
  const int*   psi_lon_in = (const int*)  d_in[7];
  float*       out        = (float*)d_out;

  transpose_w_kernel<<<(C_ * K_ * F_ + NT - 1) / NT, NT>>>(weight);

  cudaFuncSetAttribute(disco_kernel,
                       cudaFuncAttributeMaxDynamicSharedMemorySize,
                       (int)SMEM_BYTES);
  dim3 grid(6, H_, B_);
  disco_kernel<<<grid, NT, SMEM_BYTES>>>(x, psi_vals, bias,
                                         psi_lat_in, psi_lon_in, out);
}

// round 6
// speedup vs baseline: 1.3941x; 1.3941x over previous
#include <cuda_runtime.h>

// DiscreteContinuousConvS2: fused DISCO gather + channel-contraction GEMM.
// R5: crossbar-optimized — conflict-free gather (lane=wo), psi broadcast
// amortized over 4 channels, float4 staging, 2f-per-thread GEMM.

namespace {
constexpr int B_  = 2;
constexpr int C_  = 64;   // C_in
constexpr int F_  = 64;   // C_out
constexpr int H_  = 181;  // nlat
constexpr int W_  = 360;  // nlon
constexpr int K_  = 9;    // kernel functions
constexpr int J_  = 24;   // nnz per (k, lat_out)

constexpr int CCH = 8;            // channels per chunk
constexpr int NCH = C_ / CCH;     // 8 chunks
constexpr int WT  = 64;           // wo tile width
constexpr int SXP = W_ + WT;      // 424: wrap-padded x row pitch (floats)
constexpr int SXC = 3 * SXP;      // 1272: per-channel slab (3 lat rows)
constexpr int CKL = CCH * K_;     // 72 (c,k) pairs per chunk
constexpr int NT  = 256;          // threads per CTA

constexpr int SX_FLOATS = CCH * SXC;      // 10176
constexpr int SY_FLOATS = CKL * WT;       // 4608 (pitch 64, broadcast reads)
constexpr int SW_FLOATS = CKL * F_;       // 4608
constexpr size_t SMEM_BYTES =
    (size_t)(SX_FLOATS + SY_FLOATS + SW_FLOATS) * 4 + (size_t)K_ * J_ * 8;

constexpr int ROW4 = 106;                 // float4s per staged row (90 main + 16 wrap)
constexpr int NROW = CCH * 3;             // 24 staged rows per chunk
}

// weight transposed to [c*K+k][f] so per-chunk smem fill is contiguous
__device__ float g_wT[C_ * K_ * F_];

__global__ void transpose_w_kernel(const float* __restrict__ w) {
  int i = blockIdx.x * blockDim.x + threadIdx.x;
  if (i < C_ * K_ * F_) {
    int f  = i & (F_ - 1);
    int ck = i >> 6;
    // w layout: [F][C][K] -> flat f*(C*K) + c*K + k = f*576 + ck
    g_wT[i] = w[f * (C_ * K_) + ck];
  }
}

__global__ __launch_bounds__(NT, 2)
void disco_kernel(const float* __restrict__ x,
                  const float* __restrict__ psi_vals,
                  const float* __restrict__ bias,
                  const int*   __restrict__ psi_lat_in,
                  const int*   __restrict__ psi_lon_in,
                  float*       __restrict__ out) {
  extern __shared__ float smem[];
  float*  sx = smem;                       // [CCH][3][SXP]
  float*  sy = sx + SX_FLOATS;             // [CKL][64]
  float*  sw = sy + SY_FLOATS;             // [CKL][F_]
  float2* se = (float2*)(sw + SW_FLOATS);  // [K_*J_] {psi, offset-as-int}

  const int t    = threadIdx.x;
  const int lane = t & 31;
  const int warp = t >> 5;
  const int ho   = blockIdx.y;
  const int b    = blockIdx.z;
  // 6 tiles: 0,64,128,192,256, and last shifted to 296 (overlap recompute)
  const int wb = (blockIdx.x == 5) ? (W_ - WT) : blockIdx.x * WT;

  // ---- build per-ho entry table, rebased by wb ----
  if (t < K_ * J_) {
    int k = t / J_;
    int j = t - k * J_;
    int e = (k * H_ + ho) * J_ + j;
    int li  = psi_lat_in[e] - (ho - 1);       // local lat row 0..2
    int lon = psi_lon_in[e] + wb;
    if (lon >= W_) lon -= W_;                 // rebased start lon (0..359)
    int off = li * SXP + lon;                 // smem offset within channel slab
    se[t] = make_float2(psi_vals[e], __int_as_float(off));
  }

  // ---- GEMM mapping: thread owns f ∈ {f2, f2+32}, wo = wg*8 .. wg*8+7 ----
  const int f2 = lane;          // 0..31
  const int wg = warp;          // 0..7
  float accA[8], accB[8];
  {
    float bA = bias[f2];
    float bB = bias[f2 + 32];
#pragma unroll
    for (int i = 0; i < 8; i++) { accA[i] = bA; accB[i] = bB; }
  }

  for (int ch = 0; ch < NCH; ch++) {
    const int c0 = ch * CCH;
    __syncthreads();  // previous GEMM done reading sy/sw; entry table ready

    // ---- stage x slice (float4): 24 rows of 106 float4 each ----
    {
      for (int i = t; i < NROW * ROW4; i += NT) {
        int row = i / ROW4;              // 0..23  (c*3 + l)
        int q   = i - row * ROW4;        // 0..105
        int c   = row / 3;
        int l   = row - c * 3;
        int hr  = ho - 1 + l;
        hr = (hr < 0) ? 0 : (hr > H_ - 1 ? H_ - 1 : hr);
        const float4* src =
            (const float4*)(x + ((size_t)(b * C_ + c0 + c) * H_ + hr) * W_);
        int gq = (q < 90) ? q : (q - 90);          // wrap tail reads cols 0..63
        ((float4*)(sx + c * SXC + l * SXP))[q] = src[gq];
      }
    }
    // ---- stage transposed weight chunk (contiguous float4) ----
    {
      const float4* wsrc = (const float4*)(g_wT + c0 * K_ * F_);
      float4* wdst = (float4*)sw;
      for (int i = t; i < SW_FLOATS / 4; i += NT) wdst[i] = wsrc[i];
    }
    __syncthreads();

    // ---- gather: task = (k, channel-quad); lanes = wo, wo+32 ----
    // y[(cq*4+c)*9+k][wo] = sum_j psi * sx[c][off_j + wo]
    for (int task = warp; task < 2 * K_; task += 8) {
      int k  = task % K_;
      int cq = task / K_;                          // 0 or 1
      const float2* sek = se + k * J_;
      const float*  r0 = sx + (cq * 4 + 0) * SXC + lane;
      const float*  r1 = sx + (cq * 4 + 1) * SXC + lane;
      const float*  r2 = sx + (cq * 4 + 2) * SXC + lane;
      const float*  r3 = sx + (cq * 4 + 3) * SXC + lane;
      float a0 = 0.f, a1 = 0.f, a2 = 0.f, a3 = 0.f;
      float b0 = 0.f, b1 = 0.f, b2 = 0.f, b3 = 0.f;
#pragma unroll 4
      for (int j = 0; j < J_; j++) {
        float2 pe = sek[j];
        float  ps = pe.x;
        int   off = __float_as_int(pe.y);
        a0 = fmaf(ps, r0[off],      a0);
        b0 = fmaf(ps, r0[off + 32], b0);
        a1 = fmaf(ps, r1[off],      a1);
        b1 = fmaf(ps, r1[off + 32], b1);
        a2 = fmaf(ps, r2[off],      a2);
        b2 = fmaf(ps, r2[off + 32], b2);
        a3 = fmaf(ps, r3[off],      a3);
        b3 = fmaf(ps, r3[off + 32], b3);
      }
      int ckb = (cq * 4) * K_ + k;
      sy[(ckb        ) * WT + lane]      = a0;
      sy[(ckb        ) * WT + lane + 32] = b0;
      sy[(ckb +     K_) * WT + lane]      = a1;
      sy[(ckb +     K_) * WT + lane + 32] = b1;
      sy[(ckb + 2 * K_) * WT + lane]      = a2;
      sy[(ckb + 2 * K_) * WT + lane + 32] = b2;
      sy[(ckb + 3 * K_) * WT + lane]      = a3;
      sy[(ckb + 3 * K_) * WT + lane + 32] = b3;
    }
    __syncthreads();

    // ---- GEMM: acc[f][wo] += sum_ck w[ck][f] * y[ck][wo] ----
#pragma unroll 2
    for (int ck = 0; ck < CKL; ck++) {
      float wa = sw[ck * F_ + f2];
      float wc = sw[ck * F_ + f2 + 32];
      const float4* yp = (const float4*)(sy + ck * WT + (wg << 3));
      float4 y0 = yp[0], y1 = yp[1];
      accA[0] = fmaf(wa, y0.x, accA[0]);
      accA[1] = fmaf(wa, y0.y, accA[1]);
      accA[2] = fmaf(wa, y0.z, accA[2]);
      accA[3] = fmaf(wa, y0.w, accA[3]);
      accA[4] = fmaf(wa, y1.x, accA[4]);
      accA[5] = fmaf(wa, y1.y, accA[5]);
      accA[6] = fmaf(wa, y1.z, accA[6]);
      accA[7] = fmaf(wa, y1.w, accA[7]);
      accB[0] = fmaf(wc, y0.x, accB[0]);
      accB[1] = fmaf(wc, y0.y, accB[1]);
      accB[2] = fmaf(wc, y0.z, accB[2]);
      accB[3] = fmaf(wc, y0.w, accB[3]);
      accB[4] = fmaf(wc, y1.x, accB[4]);
      accB[5] = fmaf(wc, y1.y, accB[5]);
      accB[6] = fmaf(wc, y1.z, accB[6]);
      accB[7] = fmaf(wc, y1.w, accB[7]);
    }
  }

  // ---- write out[b][f][ho][wb + wg*8 .. +7] for f = f2, f2+32 ----
  {
    int wcol = wb + (wg << 3);
    float4* oA = (float4*)(out + (((size_t)(b * F_ + f2)      * H_ + ho) * W_ + wcol));
    float4* oB = (float4*)(out + (((size_t)(b * F_ + f2 + 32) * H_ + ho) * W_ + wcol));
    oA[0] = make_float4(accA[0], accA[1], accA[2], accA[3]);
    oA[1] = make_float4(accA[4], accA[5], accA[6], accA[7]);
    oB[0] = make_float4(accB[0], accB[1], accB[2], accB[3]);
    oB[1] = make_float4(accB[4], accB[5], accB[6], accB[7]);
  }
}

extern "C" void kernel_launch(void* const* d_in, const int* in_sizes, int n_in,
                              void* d_out, int out_size) {
  const float* x          = (const float*)d_in[0];
  const float* psi_vals   = (const float*)d_in[1];
  const float* weight     = (const float*)d_in[2];
  const float* bias       = (const float*)d_in[3];
  const int*   psi_lat_in = (const int*)  d_in[6];
  const int*   psi_lon_in = (const int*)  d_in[7];
  float*       out        = (float*)d_out;

  transpose_w_kernel<<<(C_ * K_ * F_ + NT - 1) / NT, NT>>>(weight);

  cudaFuncSetAttribute(disco_kernel,
                       cudaFuncAttributeMaxDynamicSharedMemorySize,
                       (int)SMEM_BYTES);
  dim3 grid(6, H_, B_);
  disco_kernel<<<grid, NT, SMEM_BYTES>>>(x, psi_vals, bias,
                                         psi_lat_in, psi_lon_in, out);
}

// round 7
// speedup vs baseline: 2.5483x; 1.8279x over previous
#include <cuda_runtime.h>

// DiscreteContinuousConvS2: fused DISCO gather + channel-contraction GEMM.
// R7: WT=128 (3 tiles), balanced per-channel gather warps, FFMA2 (f32x2) GEMM,
// transposed weight tile staged straight from gmem (no transpose pre-kernel).

namespace {
constexpr int B_  = 2;
constexpr int C_  = 64;   // C_in
constexpr int F_  = 64;   // C_out
constexpr int H_  = 181;  // nlat
constexpr int W_  = 360;  // nlon
constexpr int K_  = 9;    // kernel functions
constexpr int J_  = 24;   // nnz per (k, lat_out)

constexpr int CCH = 8;            // channels per chunk
constexpr int NCH = C_ / CCH;     // 8 chunks
constexpr int WT  = 128;          // wo tile width
constexpr int SXP = W_ + WT;      // 488: wrap-padded x row pitch (floats)
constexpr int SXC = 3 * SXP;      // 1464: per-channel slab (3 lat rows)
constexpr int CKL = CCH * K_;     // 72 (c,k) pairs per chunk
constexpr int SWP = 76;           // swT row pitch (conflict-free for LDS.128)
constexpr int NT  = 256;          // threads per CTA

constexpr int SX_FLOATS = CCH * SXC;      // 11712
constexpr int SY_FLOATS = CKL * WT;       // 9216
constexpr int SW_FLOATS = F_ * SWP;       // 4864
constexpr size_t SMEM_BYTES =
    (size_t)(SX_FLOATS + SY_FLOATS + SW_FLOATS) * 4 + (size_t)K_ * J_ * 8;

constexpr int ROW4 = 122;                 // float4s per staged row (90 + 32 wrap)
constexpr int NROW = CCH * 3;             // 24 staged rows per chunk
}

using ull = unsigned long long;

__device__ __forceinline__ void ffma2(ull& d, ull a, ull b) {
  asm("fma.rn.f32x2 %0, %1, %2, %0;" : "+l"(d) : "l"(a), "l"(b));
}
__device__ __forceinline__ ull splat2(float w) {
  ull r;
  asm("mov.b64 %0, {%1, %1};" : "=l"(r) : "f"(w));
  return r;
}

__global__ __launch_bounds__(NT, 2)
void disco_kernel(const float* __restrict__ x,
                  const float* __restrict__ psi_vals,
                  const float* __restrict__ weight,
                  const float* __restrict__ bias,
                  const int*   __restrict__ psi_lat_in,
                  const int*   __restrict__ psi_lon_in,
                  float*       __restrict__ out) {
  extern __shared__ float smem[];
  float*  sx  = smem;                       // [CCH][3][SXP]
  float*  sy  = sx + SX_FLOATS;             // [CKL][WT]
  float*  swT = sy + SY_FLOATS;             // [F_][SWP] (w transposed: [f][ck])
  float2* se  = (float2*)(swT + SW_FLOATS); // [K_*J_] {psi, offset-as-int}

  const int t    = threadIdx.x;
  const int lane = t & 31;
  const int warp = t >> 5;
  const int ho   = blockIdx.y;
  const int b    = blockIdx.z;
  // 3 tiles: 0, 128, and last shifted to 232 (24-col overlap recompute)
  const int wb = (blockIdx.x == 2) ? (W_ - WT) : blockIdx.x * WT;

  // ---- build per-ho entry table, rebased by wb ----
  if (t < K_ * J_) {
    int k = t / J_;
    int j = t - k * J_;
    int e = (k * H_ + ho) * J_ + j;
    int li  = psi_lat_in[e] - (ho - 1);       // local lat row 0..2
    int lon = psi_lon_in[e] + wb;
    if (lon >= W_) lon -= W_;                 // rebased start lon (0..359)
    int off = li * SXP + lon;                 // smem offset within channel slab
    se[t] = make_float2(psi_vals[e], __int_as_float(off));
  }

  // ---- GEMM mapping: thread owns f ∈ {lane, lane+32}, wo = warp*16..+15 ----
  const int f2  = lane;
  const int wo0 = warp << 4;
  ull accA[8], accB[8];
  {
    ull bA = splat2(bias[f2]);
    ull bB = splat2(bias[f2 + 32]);
#pragma unroll
    for (int i = 0; i < 8; i++) { accA[i] = bA; accB[i] = bB; }
  }

  for (int ch = 0; ch < NCH; ch++) {
    const int c0 = ch * CCH;
    __syncthreads();  // prev GEMM done reading sy/swT; entry table ready

    // ---- stage x slice (float4): 24 rows of 122 float4 (360 + 128 wrap) ----
    for (int i = t; i < NROW * ROW4; i += NT) {
      int row = i / ROW4;              // c*3 + l
      int q   = i - row * ROW4;        // 0..121
      int c   = row / 3;
      int l   = row - c * 3;
      int hr  = ho - 1 + l;
      hr = (hr < 0) ? 0 : (hr > H_ - 1 ? H_ - 1 : hr);
      const float4* src =
          (const float4*)(x + ((size_t)(b * C_ + c0 + c) * H_ + hr) * W_);
      int gq = (q < 90) ? q : (q - 90);          // wrap tail reads cols 0..127
      ((float4*)(sx + c * SXC + l * SXP))[q] = src[gq];
    }
    // ---- stage transposed weight tile: swT[f][i] = w[f][c0*9 + i] ----
    // weight is [F][C*K] flat; chunk slice is contiguous per f-row.
    for (int i = t; i < F_ * (CKL / 4); i += NT) {
      int f = i / (CKL / 4);           // 0..63
      int q = i - f * (CKL / 4);       // 0..17
      ((float4*)(swT + f * SWP))[q] =
          ((const float4*)(weight + f * (C_ * K_) + c0 * K_))[q];
    }
    __syncthreads();

    // ---- gather: warp = one channel (perfectly balanced, 8 warps = 8 ch) ----
    {
      const float* base = sx + warp * SXC;
#pragma unroll
      for (int k = 0; k < K_; k++) {
        const float2* sek = se + k * J_;
        float a0 = 0.f, a1 = 0.f, a2 = 0.f, a3 = 0.f;
#pragma unroll 8
        for (int j = 0; j < J_; j++) {
          float2 pe = sek[j];
          float  ps = pe.x;
          const float* p = base + __float_as_int(pe.y) + lane;
          a0 = fmaf(ps, p[0],  a0);
          a1 = fmaf(ps, p[32], a1);
          a2 = fmaf(ps, p[64], a2);
          a3 = fmaf(ps, p[96], a3);
        }
        float* yo = sy + (warp * K_ + k) * WT + lane;
        yo[0]  = a0;
        yo[32] = a1;
        yo[64] = a2;
        yo[96] = a3;
      }
    }
    __syncthreads();

    // ---- GEMM (FFMA2): acc[f][wo-pair] += w[ck][f] * y[ck][wo-pair] ----
#pragma unroll 2
    for (int ckq = 0; ckq < CKL / 4; ckq++) {
      float4 w4a = *(const float4*)(swT + f2 * SWP + (ckq << 2));
      float4 w4b = *(const float4*)(swT + (f2 + 32) * SWP + (ckq << 2));
#pragma unroll
      for (int cki = 0; cki < 4; cki++) {
        const ulonglong2* yp =
            (const ulonglong2*)(sy + ((ckq << 2) + cki) * WT + wo0);
        ulonglong2 p0 = yp[0], p1 = yp[1], p2 = yp[2], p3 = yp[3];
        float wfa = (cki == 0) ? w4a.x : (cki == 1) ? w4a.y
                  : (cki == 2) ? w4a.z : w4a.w;
        float wfb = (cki == 0) ? w4b.x : (cki == 1) ? w4b.y
                  : (cki == 2) ? w4b.z : w4b.w;
        ull wa = splat2(wfa);
        ull wb2 = splat2(wfb);
        ffma2(accA[0], wa, p0.x);  ffma2(accA[1], wa, p0.y);
        ffma2(accA[2], wa, p1.x);  ffma2(accA[3], wa, p1.y);
        ffma2(accA[4], wa, p2.x);  ffma2(accA[5], wa, p2.y);
        ffma2(accA[6], wa, p3.x);  ffma2(accA[7], wa, p3.y);
        ffma2(accB[0], wb2, p0.x); ffma2(accB[1], wb2, p0.y);
        ffma2(accB[2], wb2, p1.x); ffma2(accB[3], wb2, p1.y);
        ffma2(accB[4], wb2, p2.x); ffma2(accB[5], wb2, p2.y);
        ffma2(accB[6], wb2, p3.x); ffma2(accB[7], wb2, p3.y);
      }
    }
  }

  // ---- write out[b][f][ho][wb + wo0 .. +15] for f = f2, f2+32 ----
  {
    int wcol = wb + wo0;
    ull* oA = (ull*)(out + (((size_t)(b * F_ + f2)      * H_ + ho) * W_ + wcol));
    ull* oB = (ull*)(out + (((size_t)(b * F_ + f2 + 32) * H_ + ho) * W_ + wcol));
#pragma unroll
    for (int i = 0; i < 8; i++) { oA[i] = accA[i]; oB[i] = accB[i]; }
  }
}

extern "C" void kernel_launch(void* const* d_in, const int* in_sizes, int n_in,
                              void* d_out, int out_size) {
  const float* x          = (const float*)d_in[0];
  const float* psi_vals   = (const float*)d_in[1];
  const float* weight     = (const float*)d_in[2];
  const float* bias       = (const float*)d_in[3];
  const int*   psi_lat_in = (const int*)  d_in[6];
  const int*   psi_lon_in = (const int*)  d_in[7];
  float*       out        = (float*)d_out;

  cudaFuncSetAttribute(disco_kernel,
                       cudaFuncAttributeMaxDynamicSharedMemorySize,
                       (int)SMEM_BYTES);
  dim3 grid(3, H_, B_);
  disco_kernel<<<grid, NT, SMEM_BYTES>>>(x, psi_vals, weight, bias,
                                         psi_lat_in, psi_lon_in, out);
}